// round 2
// baseline (speedup 1.0000x reference)
#include <cuda_runtime.h>
#include <cuda_bf16.h>
#include <cstdint>

// Problem constants
#define NNODES 50000
#define IND    64
#define HID    128
#define EDIM   16
#define NTYPES 100

// Scratch (device globals; no runtime allocation allowed)
__device__ float g_agg1[NNODES * IND];    // layer1 accumulator (init = x)
__device__ float g_t1  [NNODES * HID];    // MLP intermediate
__device__ float g_h1  [NNODES * HID];    // after MLP1
__device__ float g_agg2[NNODES * HID];    // layer2 accumulator (init = h1)
__device__ float g_h2  [NNODES * HID];    // after MLP2

// ---------------------------------------------------------------------------
// vectorized global reductions (sm_90+)
// ---------------------------------------------------------------------------
__device__ __forceinline__ void red_add_v2(float* addr, float x, float y) {
    asm volatile("red.global.add.v2.f32 [%0], {%1, %2};"
                 :: "l"(addr), "f"(x), "f"(y) : "memory");
}
__device__ __forceinline__ void red_add_v4(float* addr, float x, float y, float z, float w) {
    asm volatile("red.global.add.v4.f32 [%0], {%1, %2, %3, %4};"
                 :: "l"(addr), "f"(x), "f"(y), "f"(z), "f"(w) : "memory");
}

// ---------------------------------------------------------------------------
// Edge pass 1: agg[dst] += relu(x[src] + (ea*w) @ We1^T + be1), feat dim 64.
// One warp per edge (grid-stride). Lane owns features {2*lane, 2*lane+1};
// the 2x16 weight slice lives in registers, loaded once per warp.
// ---------------------------------------------------------------------------
__global__ void edge_pass1(const float* __restrict__ x,
                           const int* __restrict__ src,
                           const int* __restrict__ dst,
                           const float* __restrict__ eattr,
                           const float* __restrict__ ew,
                           const float* __restrict__ We,   // [64,16]
                           const float* __restrict__ be,   // [64]
                           float* __restrict__ agg,
                           int E) {
    const int lane = threadIdx.x & 31;
    const int f0 = 2 * lane;

    float w0[16], w1[16];
#pragma unroll
    for (int k = 0; k < 16; k++) {
        w0[k] = We[(f0 + 0) * 16 + k];
        w1[k] = We[(f0 + 1) * 16 + k];
    }
    const float b0 = be[f0], b1 = be[f0 + 1];

    const int warpId     = (blockIdx.x * blockDim.x + threadIdx.x) >> 5;
    const int warpsTotal = (gridDim.x * blockDim.x) >> 5;

    for (int e = warpId; e < E; e += warpsTotal) {
        const int s = src[e];
        const int d = dst[e];
        const float wt = ew[e];
        float eav = 0.f;
        if (lane < 16) eav = eattr[(long long)e * 16 + lane] * wt;

        float acc0 = b0, acc1 = b1;
#pragma unroll
        for (int k = 0; k < 16; k++) {
            const float a = __shfl_sync(0xffffffffu, eav, k);
            acc0 = fmaf(a, w0[k], acc0);
            acc1 = fmaf(a, w1[k], acc1);
        }
        const float2 hx = *(const float2*)&x[(long long)s * IND + f0];
        const float m0 = fmaxf(hx.x + acc0, 0.f);
        const float m1 = fmaxf(hx.y + acc1, 0.f);
        red_add_v2(&agg[(long long)d * IND + f0], m0, m1);
    }
}

// ---------------------------------------------------------------------------
// Edge pass 2: agg[dst] += relu(h[src] + (ea*w) @ We2^T + be2), feat dim 128.
// Lane owns features {4*lane..4*lane+3}; 4x16 weight slice in registers.
// ---------------------------------------------------------------------------
__global__ void edge_pass2(const float* __restrict__ h,
                           const int* __restrict__ src,
                           const int* __restrict__ dst,
                           const float* __restrict__ eattr,
                           const float* __restrict__ ew,
                           const float* __restrict__ We,   // [128,16]
                           const float* __restrict__ be,   // [128]
                           float* __restrict__ agg,
                           int E) {
    const int lane = threadIdx.x & 31;
    const int f0 = 4 * lane;

    float wv[4][16];
    float bv[4];
#pragma unroll
    for (int r = 0; r < 4; r++) {
        bv[r] = be[f0 + r];
#pragma unroll
        for (int k = 0; k < 16; k++)
            wv[r][k] = We[(f0 + r) * 16 + k];
    }

    const int warpId     = (blockIdx.x * blockDim.x + threadIdx.x) >> 5;
    const int warpsTotal = (gridDim.x * blockDim.x) >> 5;

    for (int e = warpId; e < E; e += warpsTotal) {
        const int s = src[e];
        const int d = dst[e];
        const float wt = ew[e];
        float eav = 0.f;
        if (lane < 16) eav = eattr[(long long)e * 16 + lane] * wt;

        float acc0 = bv[0], acc1 = bv[1], acc2 = bv[2], acc3 = bv[3];
#pragma unroll
        for (int k = 0; k < 16; k++) {
            const float a = __shfl_sync(0xffffffffu, eav, k);
            acc0 = fmaf(a, wv[0][k], acc0);
            acc1 = fmaf(a, wv[1][k], acc1);
            acc2 = fmaf(a, wv[2][k], acc2);
            acc3 = fmaf(a, wv[3][k], acc3);
        }
        const float4 hx = *(const float4*)&h[(long long)s * HID + f0];
        const float m0 = fmaxf(hx.x + acc0, 0.f);
        const float m1 = fmaxf(hx.y + acc1, 0.f);
        const float m2 = fmaxf(hx.z + acc2, 0.f);
        const float m3 = fmaxf(hx.w + acc3, 0.f);
        red_add_v4(&agg[(long long)d * HID + f0], m0, m1, m2, m3);
    }
}

// ---------------------------------------------------------------------------
// Register-blocked SGEMM: C[m,n] = act( sum_k A[m,k]*W[n,k] + bias[n] )
// BM=BN=128, BK=8, 256 threads, 8x8 micro-tile per thread.
// K must be a multiple of 8 (64 or 128 here). N <= 128 (single block column).
// ---------------------------------------------------------------------------
template <bool RELU>
__global__ void sgemm_bias(const float* __restrict__ A,
                           const float* __restrict__ W,
                           const float* __restrict__ bias,
                           float* __restrict__ C,
                           int M, int N, int K) {
    const int BM = 128, BN = 128, BK = 8;
    __shared__ float As[BK][BM];
    __shared__ float Bs[BK][BN];

    const int tid = threadIdx.x;
    const int tx = tid & 15;     // 0..15 -> n micro-tile
    const int ty = tid >> 4;     // 0..15 -> m micro-tile
    const int m0 = blockIdx.y * BM;

    // loader mapping: 256 threads load 128 rows x 8 cols (4 consecutive per thread)
    const int lrow = tid >> 1;
    const int lcol = (tid & 1) * 4;

    float acc[8][8];
#pragma unroll
    for (int i = 0; i < 8; i++)
#pragma unroll
        for (int j = 0; j < 8; j++) acc[i][j] = 0.f;

    for (int k0 = 0; k0 < K; k0 += BK) {
        // A tile
        {
            const int r = m0 + lrow;
            float4 v = make_float4(0.f, 0.f, 0.f, 0.f);
            if (r < M) v = *(const float4*)&A[(long long)r * K + k0 + lcol];
            As[lcol + 0][lrow] = v.x;
            As[lcol + 1][lrow] = v.y;
            As[lcol + 2][lrow] = v.z;
            As[lcol + 3][lrow] = v.w;
        }
        // W tile
        {
            const int r = lrow;
            float4 v = make_float4(0.f, 0.f, 0.f, 0.f);
            if (r < N) v = *(const float4*)&W[(long long)r * K + k0 + lcol];
            Bs[lcol + 0][lrow] = v.x;
            Bs[lcol + 1][lrow] = v.y;
            Bs[lcol + 2][lrow] = v.z;
            Bs[lcol + 3][lrow] = v.w;
        }
        __syncthreads();

#pragma unroll
        for (int kk = 0; kk < BK; kk++) {
            float av[8], bv[8];
            *(float4*)&av[0] = *(const float4*)&As[kk][ty * 8 + 0];
            *(float4*)&av[4] = *(const float4*)&As[kk][ty * 8 + 4];
            *(float4*)&bv[0] = *(const float4*)&Bs[kk][tx * 8 + 0];
            *(float4*)&bv[4] = *(const float4*)&Bs[kk][tx * 8 + 4];
#pragma unroll
            for (int i = 0; i < 8; i++)
#pragma unroll
                for (int j = 0; j < 8; j++)
                    acc[i][j] = fmaf(av[i], bv[j], acc[i][j]);
        }
        __syncthreads();
    }

#pragma unroll
    for (int i = 0; i < 8; i++) {
        const int m = m0 + ty * 8 + i;
        if (m >= M) continue;
#pragma unroll
        for (int j = 0; j < 8; j++) {
            const int n = tx * 8 + j;
            if (n >= N) continue;
            float v = acc[i][j] + bias[n];
            if (RELU) v = fmaxf(v, 0.f);
            C[(long long)m * N + n] = v;
        }
    }
}

// ---------------------------------------------------------------------------
extern "C" void kernel_launch(void* const* d_in, const int* in_sizes, int n_in,
                              void* d_out, int out_size) {
    const float*      x     = (const float*)d_in[0];
    const int*        ei    = (const int*)d_in[1];        // int32 (JAX x64 disabled)
    const float*      eattr = (const float*)d_in[2];
    const float*      ew    = (const float*)d_in[3];
    const float*      We1   = (const float*)d_in[4];
    const float*      be1   = (const float*)d_in[5];
    const float*      W11   = (const float*)d_in[6];
    const float*      b11   = (const float*)d_in[7];
    const float*      W12   = (const float*)d_in[8];
    const float*      b12   = (const float*)d_in[9];
    const float*      We2   = (const float*)d_in[10];
    const float*      be2   = (const float*)d_in[11];
    const float*      W21   = (const float*)d_in[12];
    const float*      b21   = (const float*)d_in[13];
    const float*      W22   = (const float*)d_in[14];
    const float*      b22   = (const float*)d_in[15];
    const float*      Wo    = (const float*)d_in[16];
    const float*      bo    = (const float*)d_in[17];
    float*            out   = (float*)d_out;

    const int E = in_sizes[1] / 2;
    const int* src = ei;
    const int* dst = ei + E;

    float *agg1, *t1, *h1, *agg2, *h2;
    cudaGetSymbolAddress((void**)&agg1, g_agg1);
    cudaGetSymbolAddress((void**)&t1,   g_t1);
    cudaGetSymbolAddress((void**)&h1,   g_h1);
    cudaGetSymbolAddress((void**)&agg2, g_agg2);
    cudaGetSymbolAddress((void**)&h2,   g_h2);

    const int M = NNODES;
    const dim3 gemmGrid(1, (M + 127) / 128);
    const int EB = 1184;       // 148 SMs * 8 blocks
    const int ET = 256;

    // ---- layer 1 ----
    cudaMemcpyAsync(agg1, x, (size_t)M * IND * sizeof(float),
                    cudaMemcpyDeviceToDevice, 0);
    edge_pass1<<<EB, ET>>>(x, src, dst, eattr, ew, We1, be1, agg1, E);
    sgemm_bias<true><<<gemmGrid, 256>>>(agg1, W11, b11, t1, M, HID, IND);
    sgemm_bias<true><<<gemmGrid, 256>>>(t1,   W12, b12, h1, M, HID, HID);

    // ---- layer 2 ----
    cudaMemcpyAsync(agg2, h1, (size_t)M * HID * sizeof(float),
                    cudaMemcpyDeviceToDevice, 0);
    edge_pass2<<<EB, ET>>>(h1, src, dst, eattr, ew, We2, be2, agg2, E);
    sgemm_bias<true><<<gemmGrid, 256>>>(agg2, W21, b21, t1, M, HID, HID);
    sgemm_bias<true><<<gemmGrid, 256>>>(t1,   W22, b22, h2, M, HID, HID);

    // ---- output head ----
    sgemm_bias<false><<<gemmGrid, 256>>>(h2, Wo, bo, out, M, NTYPES, HID);
}

// round 5
// speedup vs baseline: 1.2521x; 1.2521x over previous
#include <cuda_runtime.h>
#include <cuda_bf16.h>
#include <cstdint>

// Problem constants
#define NNODES 50000
#define IND    64
#define HID    128
#define EDIM   16
#define NTYPES 100

// Scratch (device globals; no runtime allocation allowed)
__device__ float g_agg1[NNODES * IND];    // layer1 accumulator (init = x)
__device__ float g_t1  [NNODES * HID];    // MLP intermediate
__device__ float g_h1  [NNODES * HID];    // after MLP1
__device__ float g_agg2[NNODES * HID];    // layer2 accumulator (init = h1)
__device__ float g_h2  [NNODES * HID];    // after MLP2

// ---------------------------------------------------------------------------
// vectorized global reductions (sm_90+)
// ---------------------------------------------------------------------------
__device__ __forceinline__ void red_add_v2(float* addr, float x, float y) {
    asm volatile("red.global.add.v2.f32 [%0], {%1, %2};"
                 :: "l"(addr), "f"(x), "f"(y) : "memory");
}
__device__ __forceinline__ void red_add_v4(float* addr, float x, float y, float z, float w) {
    asm volatile("red.global.add.v4.f32 [%0], {%1, %2, %3, %4};"
                 :: "l"(addr), "f"(x), "f"(y), "f"(z), "f"(w) : "memory");
}

// ---------------------------------------------------------------------------
// Edge pass 1 (feat dim 64): agg[dst] += relu(x[src] + (ea*w) @ We1^T + be1)
// One warp processes TWO edges per iteration. Lane owns features
// {2*lane, 2*lane+1}; the 2x16 weight slice lives in registers.
// The paired edges' 32 edge-attrs are contiguous -> one coalesced warp load.
// ---------------------------------------------------------------------------
__global__ void __launch_bounds__(128, 8)
edge_pass1(const float* __restrict__ x,
           const int* __restrict__ src,
           const int* __restrict__ dst,
           const float* __restrict__ eattr,
           const float* __restrict__ ew,
           const float* __restrict__ We,   // [64,16]
           const float* __restrict__ be,   // [64]
           float* __restrict__ agg,
           int E) {
    const int lane = threadIdx.x & 31;
    const int f0 = 2 * lane;

    float w0[16], w1[16];
#pragma unroll
    for (int k = 0; k < 16; k++) {
        w0[k] = We[(f0 + 0) * 16 + k];
        w1[k] = We[(f0 + 1) * 16 + k];
    }
    const float b0 = be[f0], b1 = be[f0 + 1];

    const int warpId     = (blockIdx.x * blockDim.x + threadIdx.x) >> 5;
    const int warpsTotal = (gridDim.x * blockDim.x) >> 5;
    const int P = E >> 1;                 // E is even (800000)

    for (int p = warpId; p < P; p += warpsTotal) {
        const int e0 = 2 * p;
        const int2   ss = *(const int2*)&src[e0];
        const int2   dd = *(const int2*)&dst[e0];
        const float2 ww = *(const float2*)&ew[e0];

        // 32 contiguous attrs = edge e0 (lanes 0-15) + edge e0+1 (lanes 16-31)
        const float wsel = (lane < 16) ? ww.x : ww.y;
        const float eav = eattr[(long long)e0 * 16 + lane] * wsel;

        // issue gathers early; consumed after the dot products
        const float2 hx0 = *(const float2*)&x[(long long)ss.x * IND + f0];
        const float2 hx1 = *(const float2*)&x[(long long)ss.y * IND + f0];

        float a00 = b0, a01 = b1;   // edge0, feats f0/f0+1
        float a10 = b0, a11 = b1;   // edge1
#pragma unroll
        for (int k = 0; k < 16; k++) {
            const float c0 = __shfl_sync(0xffffffffu, eav, k);
            const float c1 = __shfl_sync(0xffffffffu, eav, 16 + k);
            a00 = fmaf(c0, w0[k], a00);
            a01 = fmaf(c0, w1[k], a01);
            a10 = fmaf(c1, w0[k], a10);
            a11 = fmaf(c1, w1[k], a11);
        }
        red_add_v2(&agg[(long long)dd.x * IND + f0],
                   fmaxf(hx0.x + a00, 0.f), fmaxf(hx0.y + a01, 0.f));
        red_add_v2(&agg[(long long)dd.y * IND + f0],
                   fmaxf(hx1.x + a10, 0.f), fmaxf(hx1.y + a11, 0.f));
    }
}

// ---------------------------------------------------------------------------
// Edge pass 2 (feat dim 128): agg[dst] += relu(h[src] + (ea*w) @ We2^T + be2)
// Two edges per warp; lane owns features {4*lane..4*lane+3}; 4x16 weight
// slice in registers; 8 independent accumulators for ILP.
// ---------------------------------------------------------------------------
__global__ void __launch_bounds__(128, 5)
edge_pass2(const float* __restrict__ h,
           const int* __restrict__ src,
           const int* __restrict__ dst,
           const float* __restrict__ eattr,
           const float* __restrict__ ew,
           const float* __restrict__ We,   // [128,16]
           const float* __restrict__ be,   // [128]
           float* __restrict__ agg,
           int E) {
    const int lane = threadIdx.x & 31;
    const int f0 = 4 * lane;

    float wv[4][16];
    float bv[4];
#pragma unroll
    for (int r = 0; r < 4; r++) {
        bv[r] = be[f0 + r];
#pragma unroll
        for (int k = 0; k < 16; k++)
            wv[r][k] = We[(f0 + r) * 16 + k];
    }

    const int warpId     = (blockIdx.x * blockDim.x + threadIdx.x) >> 5;
    const int warpsTotal = (gridDim.x * blockDim.x) >> 5;
    const int P = E >> 1;

    for (int p = warpId; p < P; p += warpsTotal) {
        const int e0 = 2 * p;
        const int2   ss = *(const int2*)&src[e0];
        const int2   dd = *(const int2*)&dst[e0];
        const float2 ww = *(const float2*)&ew[e0];

        const float wsel = (lane < 16) ? ww.x : ww.y;
        const float eav = eattr[(long long)e0 * 16 + lane] * wsel;

        // issue both gathers early (L2 latency hidden under the FMA block)
        const float4 hx0 = *(const float4*)&h[(long long)ss.x * HID + f0];
        const float4 hx1 = *(const float4*)&h[(long long)ss.y * HID + f0];

        float a0[4], a1[4];
#pragma unroll
        for (int r = 0; r < 4; r++) { a0[r] = bv[r]; a1[r] = bv[r]; }

#pragma unroll
        for (int k = 0; k < 16; k++) {
            const float c0 = __shfl_sync(0xffffffffu, eav, k);
            const float c1 = __shfl_sync(0xffffffffu, eav, 16 + k);
#pragma unroll
            for (int r = 0; r < 4; r++) {
                a0[r] = fmaf(c0, wv[r][k], a0[r]);
                a1[r] = fmaf(c1, wv[r][k], a1[r]);
            }
        }
        red_add_v4(&agg[(long long)dd.x * HID + f0],
                   fmaxf(hx0.x + a0[0], 0.f), fmaxf(hx0.y + a0[1], 0.f),
                   fmaxf(hx0.z + a0[2], 0.f), fmaxf(hx0.w + a0[3], 0.f));
        red_add_v4(&agg[(long long)dd.y * HID + f0],
                   fmaxf(hx1.x + a1[0], 0.f), fmaxf(hx1.y + a1[1], 0.f),
                   fmaxf(hx1.z + a1[2], 0.f), fmaxf(hx1.w + a1[3], 0.f));
    }
}

// ---------------------------------------------------------------------------
// Register-blocked SGEMM: C[m,n] = act( sum_k A[m,k]*W[n,k] + bias[n] )
// BM=BN=128, BK=8, 256 threads, 8x8 micro-tile per thread.
// ---------------------------------------------------------------------------
template <bool RELU>
__global__ void sgemm_bias(const float* __restrict__ A,
                           const float* __restrict__ W,
                           const float* __restrict__ bias,
                           float* __restrict__ C,
                           int M, int N, int K) {
    const int BM = 128, BK = 8;
    __shared__ float As[BK][BM];
    __shared__ float Bs[BK][BM];

    const int tid = threadIdx.x;
    const int tx = tid & 15;     // n micro-tile
    const int ty = tid >> 4;     // m micro-tile
    const int m0 = blockIdx.y * BM;

    const int lrow = tid >> 1;
    const int lcol = (tid & 1) * 4;

    float acc[8][8];
#pragma unroll
    for (int i = 0; i < 8; i++)
#pragma unroll
        for (int j = 0; j < 8; j++) acc[i][j] = 0.f;

    for (int k0 = 0; k0 < K; k0 += BK) {
        {
            const int r = m0 + lrow;
            float4 v = make_float4(0.f, 0.f, 0.f, 0.f);
            if (r < M) v = *(const float4*)&A[(long long)r * K + k0 + lcol];
            As[lcol + 0][lrow] = v.x;
            As[lcol + 1][lrow] = v.y;
            As[lcol + 2][lrow] = v.z;
            As[lcol + 3][lrow] = v.w;
        }
        {
            const int r = lrow;
            float4 v = make_float4(0.f, 0.f, 0.f, 0.f);
            if (r < N) v = *(const float4*)&W[(long long)r * K + k0 + lcol];
            Bs[lcol + 0][lrow] = v.x;
            Bs[lcol + 1][lrow] = v.y;
            Bs[lcol + 2][lrow] = v.z;
            Bs[lcol + 3][lrow] = v.w;
        }
        __syncthreads();

#pragma unroll
        for (int kk = 0; kk < BK; kk++) {
            float av[8], bv[8];
            *(float4*)&av[0] = *(const float4*)&As[kk][ty * 8 + 0];
            *(float4*)&av[4] = *(const float4*)&As[kk][ty * 8 + 4];
            *(float4*)&bv[0] = *(const float4*)&Bs[kk][tx * 8 + 0];
            *(float4*)&bv[4] = *(const float4*)&Bs[kk][tx * 8 + 4];
#pragma unroll
            for (int i = 0; i < 8; i++)
#pragma unroll
                for (int j = 0; j < 8; j++)
                    acc[i][j] = fmaf(av[i], bv[j], acc[i][j]);
        }
        __syncthreads();
    }

#pragma unroll
    for (int i = 0; i < 8; i++) {
        const int m = m0 + ty * 8 + i;
        if (m >= M) continue;
#pragma unroll
        for (int j = 0; j < 8; j++) {
            const int n = tx * 8 + j;
            if (n >= N) continue;
            float v = acc[i][j] + bias[n];
            if (RELU) v = fmaxf(v, 0.f);
            C[(long long)m * N + n] = v;
        }
    }
}

// ---------------------------------------------------------------------------
extern "C" void kernel_launch(void* const* d_in, const int* in_sizes, int n_in,
                              void* d_out, int out_size) {
    const float*      x     = (const float*)d_in[0];
    const int*        ei    = (const int*)d_in[1];        // int32 (JAX x64 disabled)
    const float*      eattr = (const float*)d_in[2];
    const float*      ew    = (const float*)d_in[3];
    const float*      We1   = (const float*)d_in[4];
    const float*      be1   = (const float*)d_in[5];
    const float*      W11   = (const float*)d_in[6];
    const float*      b11   = (const float*)d_in[7];
    const float*      W12   = (const float*)d_in[8];
    const float*      b12   = (const float*)d_in[9];
    const float*      We2   = (const float*)d_in[10];
    const float*      be2   = (const float*)d_in[11];
    const float*      W21   = (const float*)d_in[12];
    const float*      b21   = (const float*)d_in[13];
    const float*      W22   = (const float*)d_in[14];
    const float*      b22   = (const float*)d_in[15];
    const float*      Wo    = (const float*)d_in[16];
    const float*      bo    = (const float*)d_in[17];
    float*            out   = (float*)d_out;

    const int E = in_sizes[1] / 2;
    const int* src = ei;
    const int* dst = ei + E;

    float *agg1, *t1, *h1, *agg2, *h2;
    cudaGetSymbolAddress((void**)&agg1, g_agg1);
    cudaGetSymbolAddress((void**)&t1,   g_t1);
    cudaGetSymbolAddress((void**)&h1,   g_h1);
    cudaGetSymbolAddress((void**)&agg2, g_agg2);
    cudaGetSymbolAddress((void**)&h2,   g_h2);

    const int M = NNODES;
    const dim3 gemmGrid(1, (M + 127) / 128);
    const int ET = 128;
    const int EB1 = 148 * 8;   // matches __launch_bounds__(128, 8)
    const int EB2 = 148 * 5;   // matches __launch_bounds__(128, 5)

    // ---- layer 1 ----
    cudaMemcpyAsync(agg1, x, (size_t)M * IND * sizeof(float),
                    cudaMemcpyDeviceToDevice, 0);
    edge_pass1<<<EB1, ET>>>(x, src, dst, eattr, ew, We1, be1, agg1, E);
    sgemm_bias<true><<<gemmGrid, 256>>>(agg1, W11, b11, t1, M, HID, IND);
    sgemm_bias<true><<<gemmGrid, 256>>>(t1,   W12, b12, h1, M, HID, HID);

    // ---- layer 2 ----
    cudaMemcpyAsync(agg2, h1, (size_t)M * HID * sizeof(float),
                    cudaMemcpyDeviceToDevice, 0);
    edge_pass2<<<EB2, ET>>>(h1, src, dst, eattr, ew, We2, be2, agg2, E);
    sgemm_bias<true><<<gemmGrid, 256>>>(agg2, W21, b21, t1, M, HID, HID);
    sgemm_bias<true><<<gemmGrid, 256>>>(t1,   W22, b22, h2, M, HID, HID);

    // ---- output head ----
    sgemm_bias<false><<<gemmGrid, 256>>>(h2, Wo, bo, out, M, NTYPES, HID);
}

// round 8
// speedup vs baseline: 1.7387x; 1.3886x over previous
#include <cuda_runtime.h>
#include <cuda_bf16.h>
#include <cstdint>

// Problem constants
#define NNODES 50000
#define IND    64
#define HID    128
#define EDIM   16
#define NTYPES 100

// Scratch (device globals; no runtime allocation allowed)
__device__ float g_agg1[NNODES * IND];    // layer1 accumulator (init = x)
__device__ float g_t1  [NNODES * HID];    // MLP intermediate
__device__ float g_h1  [NNODES * HID];    // after MLP1
__device__ float g_agg2[NNODES * HID];    // layer2 accumulator (init = h1)
__device__ float g_h2  [NNODES * HID];    // after MLP2

// ---------------------------------------------------------------------------
// vectorized global reductions (sm_90+)
// ---------------------------------------------------------------------------
__device__ __forceinline__ void red_add_v2(float* addr, float x, float y) {
    asm volatile("red.global.add.v2.f32 [%0], {%1, %2};"
                 :: "l"(addr), "f"(x), "f"(y) : "memory");
}
__device__ __forceinline__ void red_add_v4(float* addr, float x, float y, float z, float w) {
    asm volatile("red.global.add.v4.f32 [%0], {%1, %2, %3, %4};"
                 :: "l"(addr), "f"(x), "f"(y), "f"(z), "f"(w) : "memory");
}

__device__ __forceinline__ unsigned f2tf32(float f) {
    unsigned u;
    asm("cvt.rna.tf32.f32 %0, %1;" : "=r"(u) : "f"(f));
    return u;
}

// ---------------------------------------------------------------------------
// Edge pass 1 (feat dim 64): agg[dst] += relu(x[src] + (ea*w) @ We1^T + be1)
// One warp processes TWO edges per iteration. Lane owns features
// {2*lane, 2*lane+1}; the 2x16 weight slice lives in registers.
// ---------------------------------------------------------------------------
__global__ void __launch_bounds__(128, 8)
edge_pass1(const float* __restrict__ x,
           const int* __restrict__ src,
           const int* __restrict__ dst,
           const float* __restrict__ eattr,
           const float* __restrict__ ew,
           const float* __restrict__ We,   // [64,16]
           const float* __restrict__ be,   // [64]
           float* __restrict__ agg,
           int E) {
    const int lane = threadIdx.x & 31;
    const int f0 = 2 * lane;

    float w0[16], w1[16];
#pragma unroll
    for (int k = 0; k < 16; k++) {
        w0[k] = We[(f0 + 0) * 16 + k];
        w1[k] = We[(f0 + 1) * 16 + k];
    }
    const float b0 = be[f0], b1 = be[f0 + 1];

    const int warpId     = (blockIdx.x * blockDim.x + threadIdx.x) >> 5;
    const int warpsTotal = (gridDim.x * blockDim.x) >> 5;
    const int P = E >> 1;

    for (int p = warpId; p < P; p += warpsTotal) {
        const int e0 = 2 * p;
        const int2   ss = *(const int2*)&src[e0];
        const int2   dd = *(const int2*)&dst[e0];
        const float2 ww = *(const float2*)&ew[e0];

        const float wsel = (lane < 16) ? ww.x : ww.y;
        const float eav = eattr[(long long)e0 * 16 + lane] * wsel;

        const float2 hx0 = *(const float2*)&x[(long long)ss.x * IND + f0];
        const float2 hx1 = *(const float2*)&x[(long long)ss.y * IND + f0];

        float a00 = b0, a01 = b1;
        float a10 = b0, a11 = b1;
#pragma unroll
        for (int k = 0; k < 16; k++) {
            const float c0 = __shfl_sync(0xffffffffu, eav, k);
            const float c1 = __shfl_sync(0xffffffffu, eav, 16 + k);
            a00 = fmaf(c0, w0[k], a00);
            a01 = fmaf(c0, w1[k], a01);
            a10 = fmaf(c1, w0[k], a10);
            a11 = fmaf(c1, w1[k], a11);
        }
        red_add_v2(&agg[(long long)dd.x * IND + f0],
                   fmaxf(hx0.x + a00, 0.f), fmaxf(hx0.y + a01, 0.f));
        red_add_v2(&agg[(long long)dd.y * IND + f0],
                   fmaxf(hx1.x + a10, 0.f), fmaxf(hx1.y + a11, 0.f));
    }
}

// ---------------------------------------------------------------------------
// Edge pass 2 (feat dim 128): same structure, lane owns 4 features.
// ---------------------------------------------------------------------------
__global__ void __launch_bounds__(128, 5)
edge_pass2(const float* __restrict__ h,
           const int* __restrict__ src,
           const int* __restrict__ dst,
           const float* __restrict__ eattr,
           const float* __restrict__ ew,
           const float* __restrict__ We,   // [128,16]
           const float* __restrict__ be,   // [128]
           float* __restrict__ agg,
           int E) {
    const int lane = threadIdx.x & 31;
    const int f0 = 4 * lane;

    float wv[4][16];
    float bv[4];
#pragma unroll
    for (int r = 0; r < 4; r++) {
        bv[r] = be[f0 + r];
#pragma unroll
        for (int k = 0; k < 16; k++)
            wv[r][k] = We[(f0 + r) * 16 + k];
    }

    const int warpId     = (blockIdx.x * blockDim.x + threadIdx.x) >> 5;
    const int warpsTotal = (gridDim.x * blockDim.x) >> 5;
    const int P = E >> 1;

    for (int p = warpId; p < P; p += warpsTotal) {
        const int e0 = 2 * p;
        const int2   ss = *(const int2*)&src[e0];
        const int2   dd = *(const int2*)&dst[e0];
        const float2 ww = *(const float2*)&ew[e0];

        const float wsel = (lane < 16) ? ww.x : ww.y;
        const float eav = eattr[(long long)e0 * 16 + lane] * wsel;

        const float4 hx0 = *(const float4*)&h[(long long)ss.x * HID + f0];
        const float4 hx1 = *(const float4*)&h[(long long)ss.y * HID + f0];

        float a0[4], a1[4];
#pragma unroll
        for (int r = 0; r < 4; r++) { a0[r] = bv[r]; a1[r] = bv[r]; }

#pragma unroll
        for (int k = 0; k < 16; k++) {
            const float c0 = __shfl_sync(0xffffffffu, eav, k);
            const float c1 = __shfl_sync(0xffffffffu, eav, 16 + k);
#pragma unroll
            for (int r = 0; r < 4; r++) {
                a0[r] = fmaf(c0, wv[r][k], a0[r]);
                a1[r] = fmaf(c1, wv[r][k], a1[r]);
            }
        }
        red_add_v4(&agg[(long long)dd.x * HID + f0],
                   fmaxf(hx0.x + a0[0], 0.f), fmaxf(hx0.y + a0[1], 0.f),
                   fmaxf(hx0.z + a0[2], 0.f), fmaxf(hx0.w + a0[3], 0.f));
        red_add_v4(&agg[(long long)dd.y * HID + f0],
                   fmaxf(hx1.x + a1[0], 0.f), fmaxf(hx1.y + a1[1], 0.f),
                   fmaxf(hx1.z + a1[2], 0.f), fmaxf(hx1.w + a1[3], 0.f));
    }
}

// ---------------------------------------------------------------------------
// TF32 tensor-core GEMM: C[m,n] = act( sum_k A[m,k]*W[n,k] + bias[n] )
// BM=128, BN=128, BK=16. 256 threads = 8 warps (4m x 2n), warp tile 32x64,
// built from mma.sync.m16n8k8.tf32 (2x8 mma tiles, fp32 accumulate).
// Inputs rounded to tf32 (cvt.rna) once at the smem staging step.
// ---------------------------------------------------------------------------
#define SPITCH 20   // smem row pitch in floats (conflict-free, 16B aligned)

template <bool RELU>
__global__ void __launch_bounds__(256, 2)
mma_gemm(const float* __restrict__ A,
         const float* __restrict__ W,
         const float* __restrict__ bias,
         float* __restrict__ C,
         int M, int N, int K) {
    __shared__ unsigned As[128 * SPITCH];   // [m][k] tf32 bits
    __shared__ unsigned Ws[128 * SPITCH];   // [n][k] tf32 bits

    const int tid  = threadIdx.x;
    const int lane = tid & 31;
    const int wid  = tid >> 5;
    const int wm   = wid >> 1;      // 0..3 -> 32-row warp tile
    const int wn   = wid & 1;       // 0..1 -> 64-col warp tile
    const int m0   = blockIdx.y * 128;

    const int lrow = tid >> 1;          // 0..127
    const int lseg = (tid & 1) * 8;     // 0 or 8

    const int gid  = lane >> 2;         // 0..7
    const int qid  = lane & 3;          // 0..3

    float acc[2][8][4];
#pragma unroll
    for (int i = 0; i < 2; i++)
#pragma unroll
        for (int j = 0; j < 8; j++)
#pragma unroll
            for (int v = 0; v < 4; v++) acc[i][j][v] = 0.f;

    for (int k0 = 0; k0 < K; k0 += 16) {
        // stage A tile [128 x 16] (rows m0..m0+127), tf32-rounded
        {
            const int r = m0 + lrow;
            float4 v0 = make_float4(0.f, 0.f, 0.f, 0.f);
            float4 v1 = v0;
            if (r < M) {
                const float* p = &A[(long long)r * K + k0 + lseg];
                v0 = *(const float4*)p;
                v1 = *(const float4*)(p + 4);
            }
            unsigned* dstp = &As[lrow * SPITCH + lseg];
            dstp[0] = f2tf32(v0.x); dstp[1] = f2tf32(v0.y);
            dstp[2] = f2tf32(v0.z); dstp[3] = f2tf32(v0.w);
            dstp[4] = f2tf32(v1.x); dstp[5] = f2tf32(v1.y);
            dstp[6] = f2tf32(v1.z); dstp[7] = f2tf32(v1.w);
        }
        // stage W tile [128 x 16] (rows 0..N-1, zero-padded)
        {
            const int r = lrow;
            float4 v0 = make_float4(0.f, 0.f, 0.f, 0.f);
            float4 v1 = v0;
            if (r < N) {
                const float* p = &W[(long long)r * K + k0 + lseg];
                v0 = *(const float4*)p;
                v1 = *(const float4*)(p + 4);
            }
            unsigned* dstp = &Ws[lrow * SPITCH + lseg];
            dstp[0] = f2tf32(v0.x); dstp[1] = f2tf32(v0.y);
            dstp[2] = f2tf32(v0.z); dstp[3] = f2tf32(v0.w);
            dstp[4] = f2tf32(v1.x); dstp[5] = f2tf32(v1.y);
            dstp[6] = f2tf32(v1.z); dstp[7] = f2tf32(v1.w);
        }
        __syncthreads();

#pragma unroll
        for (int kk = 0; kk < 16; kk += 8) {
            unsigned af[2][4];
#pragma unroll
            for (int mt = 0; mt < 2; mt++) {
                const int r = wm * 32 + mt * 16 + gid;
                af[mt][0] = As[(r    ) * SPITCH + kk + qid    ];
                af[mt][1] = As[(r + 8) * SPITCH + kk + qid    ];
                af[mt][2] = As[(r    ) * SPITCH + kk + qid + 4];
                af[mt][3] = As[(r + 8) * SPITCH + kk + qid + 4];
            }
            unsigned bf[8][2];
#pragma unroll
            for (int nt = 0; nt < 8; nt++) {
                const int c = wn * 64 + nt * 8 + gid;
                bf[nt][0] = Ws[c * SPITCH + kk + qid    ];
                bf[nt][1] = Ws[c * SPITCH + kk + qid + 4];
            }
#pragma unroll
            for (int mt = 0; mt < 2; mt++)
#pragma unroll
                for (int nt = 0; nt < 8; nt++) {
                    asm volatile(
                        "mma.sync.aligned.m16n8k8.row.col.f32.tf32.tf32.f32 "
                        "{%0,%1,%2,%3}, {%4,%5,%6,%7}, {%8,%9}, {%0,%1,%2,%3};"
                        : "+f"(acc[mt][nt][0]), "+f"(acc[mt][nt][1]),
                          "+f"(acc[mt][nt][2]), "+f"(acc[mt][nt][3])
                        : "r"(af[mt][0]), "r"(af[mt][1]),
                          "r"(af[mt][2]), "r"(af[mt][3]),
                          "r"(bf[nt][0]), "r"(bf[nt][1]));
                }
        }
        __syncthreads();
    }

    // epilogue: bias + activation + store
#pragma unroll
    for (int mt = 0; mt < 2; mt++) {
        const int rbase = m0 + wm * 32 + mt * 16 + gid;
#pragma unroll
        for (int nt = 0; nt < 8; nt++) {
            const int n = wn * 64 + nt * 8 + 2 * qid;
#pragma unroll
            for (int half = 0; half < 2; half++) {
                const int m = rbase + half * 8;
                if (m >= M) continue;
                float v0 = acc[mt][nt][2 * half + 0];
                float v1 = acc[mt][nt][2 * half + 1];
                if (n < N) {
                    float o = v0 + bias[n];
                    if (RELU) o = fmaxf(o, 0.f);
                    C[(long long)m * N + n] = o;
                }
                if (n + 1 < N) {
                    float o = v1 + bias[n + 1];
                    if (RELU) o = fmaxf(o, 0.f);
                    C[(long long)m * N + n + 1] = o;
                }
            }
        }
    }
}

// ---------------------------------------------------------------------------
extern "C" void kernel_launch(void* const* d_in, const int* in_sizes, int n_in,
                              void* d_out, int out_size) {
    const float*      x     = (const float*)d_in[0];
    const int*        ei    = (const int*)d_in[1];        // int32 (JAX x64 disabled)
    const float*      eattr = (const float*)d_in[2];
    const float*      ew    = (const float*)d_in[3];
    const float*      We1   = (const float*)d_in[4];
    const float*      be1   = (const float*)d_in[5];
    const float*      W11   = (const float*)d_in[6];
    const float*      b11   = (const float*)d_in[7];
    const float*      W12   = (const float*)d_in[8];
    const float*      b12   = (const float*)d_in[9];
    const float*      We2   = (const float*)d_in[10];
    const float*      be2   = (const float*)d_in[11];
    const float*      W21   = (const float*)d_in[12];
    const float*      b21   = (const float*)d_in[13];
    const float*      W22   = (const float*)d_in[14];
    const float*      b22   = (const float*)d_in[15];
    const float*      Wo    = (const float*)d_in[16];
    const float*      bo    = (const float*)d_in[17];
    float*            out   = (float*)d_out;

    const int E = in_sizes[1] / 2;
    const int* src = ei;
    const int* dst = ei + E;

    float *agg1, *t1, *h1, *agg2, *h2;
    cudaGetSymbolAddress((void**)&agg1, g_agg1);
    cudaGetSymbolAddress((void**)&t1,   g_t1);
    cudaGetSymbolAddress((void**)&h1,   g_h1);
    cudaGetSymbolAddress((void**)&agg2, g_agg2);
    cudaGetSymbolAddress((void**)&h2,   g_h2);

    const int M = NNODES;
    const dim3 gemmGrid(1, (M + 127) / 128);
    const int ET = 128;
    const int EB1 = 148 * 8;
    const int EB2 = 148 * 5;

    // ---- layer 1 ----
    cudaMemcpyAsync(agg1, x, (size_t)M * IND * sizeof(float),
                    cudaMemcpyDeviceToDevice, 0);
    edge_pass1<<<EB1, ET>>>(x, src, dst, eattr, ew, We1, be1, agg1, E);
    mma_gemm<true><<<gemmGrid, 256>>>(agg1, W11, b11, t1, M, HID, IND);
    mma_gemm<true><<<gemmGrid, 256>>>(t1,   W12, b12, h1, M, HID, HID);

    // ---- layer 2 ----
    cudaMemcpyAsync(agg2, h1, (size_t)M * HID * sizeof(float),
                    cudaMemcpyDeviceToDevice, 0);
    edge_pass2<<<EB2, ET>>>(h1, src, dst, eattr, ew, We2, be2, agg2, E);
    mma_gemm<true><<<gemmGrid, 256>>>(agg2, W21, b21, t1, M, HID, HID);
    mma_gemm<true><<<gemmGrid, 256>>>(t1,   W22, b22, h2, M, HID, HID);

    // ---- output head ----
    mma_gemm<false><<<gemmGrid, 256>>>(h2, Wo, bo, out, M, NTYPES, HID);
}

// round 9
// speedup vs baseline: 2.1009x; 1.2083x over previous
#include <cuda_runtime.h>
#include <cuda_bf16.h>
#include <cstdint>

// Problem constants
#define NNODES 50000
#define IND    64
#define HID    128
#define EDIM   16
#define NTYPES 100

// Scratch (device globals; no runtime allocation allowed)
__device__ float g_agg1[NNODES * IND];    // layer1 accumulator (init = x)
__device__ float g_t1  [NNODES * HID];    // MLP intermediate
__device__ float g_h1  [NNODES * HID];    // after MLP1
__device__ float g_agg2[NNODES * HID];    // layer2 accumulator (init = h1)
__device__ float g_h2  [NNODES * HID];    // after MLP2

// ---------------------------------------------------------------------------
__device__ __forceinline__ void red_add_v4(float* addr, float x, float y, float z, float w) {
    asm volatile("red.global.add.v4.f32 [%0], {%1, %2, %3, %4};"
                 :: "l"(addr), "f"(x), "f"(y), "f"(z), "f"(w) : "memory");
}

__device__ __forceinline__ unsigned f2tf32(float f) {
    unsigned u;
    asm("cvt.rna.tf32.f32 %0, %1;" : "=r"(u) : "f"(f));
    return u;
}

__device__ __forceinline__ void mma_tf32(float* c, const unsigned* a, const unsigned* b) {
    asm volatile(
        "mma.sync.aligned.m16n8k8.row.col.f32.tf32.tf32.f32 "
        "{%0,%1,%2,%3}, {%4,%5,%6,%7}, {%8,%9}, {%0,%1,%2,%3};"
        : "+f"(c[0]), "+f"(c[1]), "+f"(c[2]), "+f"(c[3])
        : "r"(a[0]), "r"(a[1]), "r"(a[2]), "r"(a[3]),
          "r"(b[0]), "r"(b[1]));
}

// ===========================================================================
// Edge pass 2 (feat dim 128), MMA-fused.
// Block = 256 threads, tile = 128 edges.
//   phase A: stage EA = eattr*ew (128x16 tf32) into smem
//   phase B: emb = EA @ We2^T + be2 via m16n8k8 tf32 MMA -> smem (pitch 136)
//   phase C: warp-per-edge: red.v4( agg[dst], relu(emb + h[src]) )
// Dynamic smem: sA 128*17 u32 | sW 128*17 u32 | sE 128*136 f32  = 87040 B
// ===========================================================================
#define PA 17
#define PE2 136
#define EP2_SMEM ((128*PA + 128*PA + 128*PE2) * 4)

__global__ void __launch_bounds__(256, 2)
edge_pass2_mma(const float* __restrict__ h,
               const int* __restrict__ src,
               const int* __restrict__ dst,
               const float* __restrict__ eattr,
               const float* __restrict__ ew,
               const float* __restrict__ We,   // [128,16]
               const float* __restrict__ be,   // [128]
               float* __restrict__ agg,
               int E) {
    extern __shared__ float smem[];
    unsigned* sA = (unsigned*)smem;            // [128][PA]
    unsigned* sW = sA + 128 * PA;              // [128][PA]
    float*    sE = (float*)(sW + 128 * PA);    // [128][PE2]

    const int tid  = threadIdx.x;
    const int lane = tid & 31;
    const int wid  = tid >> 5;
    const int wm   = wid >> 1;     // 0..3 : 32-edge group
    const int wn   = wid & 1;      // 0..1 : 64-feat group
    const int gid  = lane >> 2;    // 0..7
    const int qid  = lane & 3;     // 0..3

    const int lrow = tid >> 1;         // 0..127
    const int lseg = (tid & 1) * 8;    // 0 / 8

    // stage We2 (tf32) once
    {
        const float* p = &We[lrow * 16 + lseg];
        float4 v0 = *(const float4*)p;
        float4 v1 = *(const float4*)(p + 4);
        unsigned* dp = &sW[lrow * PA + lseg];
        dp[0]=f2tf32(v0.x); dp[1]=f2tf32(v0.y); dp[2]=f2tf32(v0.z); dp[3]=f2tf32(v0.w);
        dp[4]=f2tf32(v1.x); dp[5]=f2tf32(v1.y); dp[6]=f2tf32(v1.z); dp[7]=f2tf32(v1.w);
    }
    __syncthreads();

    const int numTiles = (E + 127) >> 7;
    for (int t = blockIdx.x; t < numTiles; t += gridDim.x) {
        const int base = t << 7;

        // ---- phase A: stage EA tile ----
        {
            const int ge = base + lrow;
            float4 v0 = make_float4(0.f,0.f,0.f,0.f), v1 = v0;
            if (ge < E) {
                const float wt = ew[ge];
                const float* p = &eattr[(long long)ge * 16 + lseg];
                v0 = *(const float4*)p;
                v1 = *(const float4*)(p + 4);
                v0.x*=wt; v0.y*=wt; v0.z*=wt; v0.w*=wt;
                v1.x*=wt; v1.y*=wt; v1.z*=wt; v1.w*=wt;
            }
            unsigned* dp = &sA[lrow * PA + lseg];
            dp[0]=f2tf32(v0.x); dp[1]=f2tf32(v0.y); dp[2]=f2tf32(v0.z); dp[3]=f2tf32(v0.w);
            dp[4]=f2tf32(v1.x); dp[5]=f2tf32(v1.y); dp[6]=f2tf32(v1.z); dp[7]=f2tf32(v1.w);
        }
        __syncthreads();

        // ---- phase B: MMA, acc initialized with bias ----
        float acc[2][8][4];
#pragma unroll
        for (int nt = 0; nt < 8; nt++) {
            const int n = wn * 64 + nt * 8 + 2 * qid;
            const float b0 = __ldg(&be[n]);
            const float b1 = __ldg(&be[n + 1]);
#pragma unroll
            for (int mt = 0; mt < 2; mt++) {
                acc[mt][nt][0] = b0; acc[mt][nt][1] = b1;
                acc[mt][nt][2] = b0; acc[mt][nt][3] = b1;
            }
        }
#pragma unroll
        for (int kk = 0; kk < 16; kk += 8) {
            unsigned af[2][4];
#pragma unroll
            for (int mt = 0; mt < 2; mt++) {
                const int r = wm * 32 + mt * 16 + gid;
                af[mt][0] = sA[(r    ) * PA + kk + qid    ];
                af[mt][1] = sA[(r + 8) * PA + kk + qid    ];
                af[mt][2] = sA[(r    ) * PA + kk + qid + 4];
                af[mt][3] = sA[(r + 8) * PA + kk + qid + 4];
            }
            unsigned bf[8][2];
#pragma unroll
            for (int nt = 0; nt < 8; nt++) {
                const int c = wn * 64 + nt * 8 + gid;
                bf[nt][0] = sW[c * PA + kk + qid    ];
                bf[nt][1] = sW[c * PA + kk + qid + 4];
            }
#pragma unroll
            for (int mt = 0; mt < 2; mt++)
#pragma unroll
                for (int nt = 0; nt < 8; nt++)
                    mma_tf32(acc[mt][nt], af[mt], bf[nt]);
        }
        // epilogue: fragments -> sE
#pragma unroll
        for (int mt = 0; mt < 2; mt++) {
            const int r0 = wm * 32 + mt * 16 + gid;
#pragma unroll
            for (int nt = 0; nt < 8; nt++) {
                const int n = wn * 64 + nt * 8 + 2 * qid;
                *(float2*)&sE[r0 * PE2 + n]       = make_float2(acc[mt][nt][0], acc[mt][nt][1]);
                *(float2*)&sE[(r0 + 8) * PE2 + n] = make_float2(acc[mt][nt][2], acc[mt][nt][3]);
            }
        }
        __syncthreads();

        // ---- phase C: gather + relu + scatter (warp per edge) ----
        const int f = 4 * lane;
#pragma unroll 2
        for (int i = 0; i < 16; i++) {
            const int el = wid * 16 + i;
            const int ge = base + el;
            if (ge < E) {
                const int s = src[ge];
                const int d = dst[ge];
                const float4 em = *(const float4*)&sE[el * PE2 + f];
                const float4 hv = *(const float4*)&h[(long long)s * HID + f];
                red_add_v4(&agg[(long long)d * HID + f],
                           fmaxf(em.x + hv.x, 0.f), fmaxf(em.y + hv.y, 0.f),
                           fmaxf(em.z + hv.z, 0.f), fmaxf(em.w + hv.w, 0.f));
            }
        }
        __syncthreads();
    }
}

// ===========================================================================
// Edge pass 1 (feat dim 64), MMA-fused. Same structure; warp tile = 16 edges
// x 64 feats (mt=1), scatter uses half-warp per edge.
// Dynamic smem: sA 128*17 u32 | sW 64*17 u32 | sE 128*72 f32 = 49920 B
// ===========================================================================
#define PE1 72
#define EP1_SMEM ((128*PA + 64*PA + 128*PE1) * 4)

__global__ void __launch_bounds__(256, 3)
edge_pass1_mma(const float* __restrict__ x,
               const int* __restrict__ src,
               const int* __restrict__ dst,
               const float* __restrict__ eattr,
               const float* __restrict__ ew,
               const float* __restrict__ We,   // [64,16]
               const float* __restrict__ be,   // [64]
               float* __restrict__ agg,
               int E) {
    extern __shared__ float smem[];
    unsigned* sA = (unsigned*)smem;            // [128][PA]
    unsigned* sW = sA + 128 * PA;              // [64][PA]
    float*    sE = (float*)(sW + 64 * PA);     // [128][PE1]

    const int tid  = threadIdx.x;
    const int lane = tid & 31;
    const int wid  = tid >> 5;
    const int gid  = lane >> 2;
    const int qid  = lane & 3;

    const int lrow = tid >> 1;
    const int lseg = (tid & 1) * 8;

    // stage We1 (tf32) once (64 rows -> threads 0..127)
    if (tid < 128) {
        const float* p = &We[lrow * 16 + lseg];
        float4 v0 = *(const float4*)p;
        float4 v1 = *(const float4*)(p + 4);
        unsigned* dp = &sW[lrow * PA + lseg];
        dp[0]=f2tf32(v0.x); dp[1]=f2tf32(v0.y); dp[2]=f2tf32(v0.z); dp[3]=f2tf32(v0.w);
        dp[4]=f2tf32(v1.x); dp[5]=f2tf32(v1.y); dp[6]=f2tf32(v1.z); dp[7]=f2tf32(v1.w);
    }
    __syncthreads();

    const int numTiles = (E + 127) >> 7;
    for (int t = blockIdx.x; t < numTiles; t += gridDim.x) {
        const int base = t << 7;

        // ---- stage EA tile ----
        {
            const int ge = base + lrow;
            float4 v0 = make_float4(0.f,0.f,0.f,0.f), v1 = v0;
            if (ge < E) {
                const float wt = ew[ge];
                const float* p = &eattr[(long long)ge * 16 + lseg];
                v0 = *(const float4*)p;
                v1 = *(const float4*)(p + 4);
                v0.x*=wt; v0.y*=wt; v0.z*=wt; v0.w*=wt;
                v1.x*=wt; v1.y*=wt; v1.z*=wt; v1.w*=wt;
            }
            unsigned* dp = &sA[lrow * PA + lseg];
            dp[0]=f2tf32(v0.x); dp[1]=f2tf32(v0.y); dp[2]=f2tf32(v0.z); dp[3]=f2tf32(v0.w);
            dp[4]=f2tf32(v1.x); dp[5]=f2tf32(v1.y); dp[6]=f2tf32(v1.z); dp[7]=f2tf32(v1.w);
        }
        __syncthreads();

        // ---- MMA: 16 edges (this warp) x 64 feats ----
        float acc[8][4];
#pragma unroll
        for (int nt = 0; nt < 8; nt++) {
            const int n = nt * 8 + 2 * qid;
            const float b0 = __ldg(&be[n]);
            const float b1 = __ldg(&be[n + 1]);
            acc[nt][0] = b0; acc[nt][1] = b1;
            acc[nt][2] = b0; acc[nt][3] = b1;
        }
#pragma unroll
        for (int kk = 0; kk < 16; kk += 8) {
            unsigned af[4];
            const int r = wid * 16 + gid;
            af[0] = sA[(r    ) * PA + kk + qid    ];
            af[1] = sA[(r + 8) * PA + kk + qid    ];
            af[2] = sA[(r    ) * PA + kk + qid + 4];
            af[3] = sA[(r + 8) * PA + kk + qid + 4];
            unsigned bf[8][2];
#pragma unroll
            for (int nt = 0; nt < 8; nt++) {
                const int c = nt * 8 + gid;
                bf[nt][0] = sW[c * PA + kk + qid    ];
                bf[nt][1] = sW[c * PA + kk + qid + 4];
            }
#pragma unroll
            for (int nt = 0; nt < 8; nt++)
                mma_tf32(acc[nt], af, bf[nt]);
        }
        {
            const int r0 = wid * 16 + gid;
#pragma unroll
            for (int nt = 0; nt < 8; nt++) {
                const int n = nt * 8 + 2 * qid;
                *(float2*)&sE[r0 * PE1 + n]       = make_float2(acc[nt][0], acc[nt][1]);
                *(float2*)&sE[(r0 + 8) * PE1 + n] = make_float2(acc[nt][2], acc[nt][3]);
            }
        }
        __syncthreads();

        // ---- gather + relu + scatter: half-warp per edge (2 edges/iter) ----
        const int half = lane >> 4;          // 0/1
        const int f = (lane & 15) * 4;       // 0..60
#pragma unroll 2
        for (int i = 0; i < 8; i++) {
            const int el = wid * 16 + 2 * i + half;
            const int ge = base + el;
            if (ge < E) {
                const int s = src[ge];
                const int d = dst[ge];
                const float4 em = *(const float4*)&sE[el * PE1 + f];
                const float4 hv = *(const float4*)&x[(long long)s * IND + f];
                red_add_v4(&agg[(long long)d * IND + f],
                           fmaxf(em.x + hv.x, 0.f), fmaxf(em.y + hv.y, 0.f),
                           fmaxf(em.z + hv.z, 0.f), fmaxf(em.w + hv.w, 0.f));
            }
        }
        __syncthreads();
    }
}

// ---------------------------------------------------------------------------
// TF32 tensor-core GEMM: C[m,n] = act( sum_k A[m,k]*W[n,k] + bias[n] )
// (unchanged from R8)
// ---------------------------------------------------------------------------
#define SPITCH 20

template <bool RELU>
__global__ void __launch_bounds__(256, 2)
mma_gemm(const float* __restrict__ A,
         const float* __restrict__ W,
         const float* __restrict__ bias,
         float* __restrict__ C,
         int M, int N, int K) {
    __shared__ unsigned As[128 * SPITCH];
    __shared__ unsigned Ws[128 * SPITCH];

    const int tid  = threadIdx.x;
    const int lane = tid & 31;
    const int wid  = tid >> 5;
    const int wm   = wid >> 1;
    const int wn   = wid & 1;
    const int m0   = blockIdx.y * 128;

    const int lrow = tid >> 1;
    const int lseg = (tid & 1) * 8;

    const int gid  = lane >> 2;
    const int qid  = lane & 3;

    float acc[2][8][4];
#pragma unroll
    for (int i = 0; i < 2; i++)
#pragma unroll
        for (int j = 0; j < 8; j++)
#pragma unroll
            for (int v = 0; v < 4; v++) acc[i][j][v] = 0.f;

    for (int k0 = 0; k0 < K; k0 += 16) {
        {
            const int r = m0 + lrow;
            float4 v0 = make_float4(0.f,0.f,0.f,0.f), v1 = v0;
            if (r < M) {
                const float* p = &A[(long long)r * K + k0 + lseg];
                v0 = *(const float4*)p;
                v1 = *(const float4*)(p + 4);
            }
            unsigned* dstp = &As[lrow * SPITCH + lseg];
            dstp[0]=f2tf32(v0.x); dstp[1]=f2tf32(v0.y); dstp[2]=f2tf32(v0.z); dstp[3]=f2tf32(v0.w);
            dstp[4]=f2tf32(v1.x); dstp[5]=f2tf32(v1.y); dstp[6]=f2tf32(v1.z); dstp[7]=f2tf32(v1.w);
        }
        {
            const int r = lrow;
            float4 v0 = make_float4(0.f,0.f,0.f,0.f), v1 = v0;
            if (r < N) {
                const float* p = &W[(long long)r * K + k0 + lseg];
                v0 = *(const float4*)p;
                v1 = *(const float4*)(p + 4);
            }
            unsigned* dstp = &Ws[lrow * SPITCH + lseg];
            dstp[0]=f2tf32(v0.x); dstp[1]=f2tf32(v0.y); dstp[2]=f2tf32(v0.z); dstp[3]=f2tf32(v0.w);
            dstp[4]=f2tf32(v1.x); dstp[5]=f2tf32(v1.y); dstp[6]=f2tf32(v1.z); dstp[7]=f2tf32(v1.w);
        }
        __syncthreads();

#pragma unroll
        for (int kk = 0; kk < 16; kk += 8) {
            unsigned af[2][4];
#pragma unroll
            for (int mt = 0; mt < 2; mt++) {
                const int r = wm * 32 + mt * 16 + gid;
                af[mt][0] = As[(r    ) * SPITCH + kk + qid    ];
                af[mt][1] = As[(r + 8) * SPITCH + kk + qid    ];
                af[mt][2] = As[(r    ) * SPITCH + kk + qid + 4];
                af[mt][3] = As[(r + 8) * SPITCH + kk + qid + 4];
            }
            unsigned bf[8][2];
#pragma unroll
            for (int nt = 0; nt < 8; nt++) {
                const int c = wn * 64 + nt * 8 + gid;
                bf[nt][0] = Ws[c * SPITCH + kk + qid    ];
                bf[nt][1] = Ws[c * SPITCH + kk + qid + 4];
            }
#pragma unroll
            for (int mt = 0; mt < 2; mt++)
#pragma unroll
                for (int nt = 0; nt < 8; nt++)
                    mma_tf32(acc[mt][nt], af[mt], bf[nt]);
        }
        __syncthreads();
    }

#pragma unroll
    for (int mt = 0; mt < 2; mt++) {
        const int rbase = m0 + wm * 32 + mt * 16 + gid;
#pragma unroll
        for (int nt = 0; nt < 8; nt++) {
            const int n = wn * 64 + nt * 8 + 2 * qid;
#pragma unroll
            for (int half = 0; half < 2; half++) {
                const int m = rbase + half * 8;
                if (m >= M) continue;
                float v0 = acc[mt][nt][2 * half + 0];
                float v1 = acc[mt][nt][2 * half + 1];
                if (n < N) {
                    float o = v0 + bias[n];
                    if (RELU) o = fmaxf(o, 0.f);
                    C[(long long)m * N + n] = o;
                }
                if (n + 1 < N) {
                    float o = v1 + bias[n + 1];
                    if (RELU) o = fmaxf(o, 0.f);
                    C[(long long)m * N + n + 1] = o;
                }
            }
        }
    }
}

// ---------------------------------------------------------------------------
extern "C" void kernel_launch(void* const* d_in, const int* in_sizes, int n_in,
                              void* d_out, int out_size) {
    const float*      x     = (const float*)d_in[0];
    const int*        ei    = (const int*)d_in[1];        // int32 (JAX x64 disabled)
    const float*      eattr = (const float*)d_in[2];
    const float*      ew    = (const float*)d_in[3];
    const float*      We1   = (const float*)d_in[4];
    const float*      be1   = (const float*)d_in[5];
    const float*      W11   = (const float*)d_in[6];
    const float*      b11   = (const float*)d_in[7];
    const float*      W12   = (const float*)d_in[8];
    const float*      b12   = (const float*)d_in[9];
    const float*      We2   = (const float*)d_in[10];
    const float*      be2   = (const float*)d_in[11];
    const float*      W21   = (const float*)d_in[12];
    const float*      b21   = (const float*)d_in[13];
    const float*      W22   = (const float*)d_in[14];
    const float*      b22   = (const float*)d_in[15];
    const float*      Wo    = (const float*)d_in[16];
    const float*      bo    = (const float*)d_in[17];
    float*            out   = (float*)d_out;

    const int E = in_sizes[1] / 2;
    const int* src = ei;
    const int* dst = ei + E;

    float *agg1, *t1, *h1, *agg2, *h2;
    cudaGetSymbolAddress((void**)&agg1, g_agg1);
    cudaGetSymbolAddress((void**)&t1,   g_t1);
    cudaGetSymbolAddress((void**)&h1,   g_h1);
    cudaGetSymbolAddress((void**)&agg2, g_agg2);
    cudaGetSymbolAddress((void**)&h2,   g_h2);

    static bool attrSet = false;
    if (!attrSet) {
        cudaFuncSetAttribute(edge_pass1_mma,
                             cudaFuncAttributeMaxDynamicSharedMemorySize, EP1_SMEM);
        cudaFuncSetAttribute(edge_pass2_mma,
                             cudaFuncAttributeMaxDynamicSharedMemorySize, EP2_SMEM);
        attrSet = true;
    }

    const int M = NNODES;
    const dim3 gemmGrid(1, (M + 127) / 128);
    const int EB1 = 148 * 3;   // matches __launch_bounds__(256,3)
    const int EB2 = 148 * 2;   // matches __launch_bounds__(256,2)

    // ---- layer 1 ----
    cudaMemcpyAsync(agg1, x, (size_t)M * IND * sizeof(float),
                    cudaMemcpyDeviceToDevice, 0);
    edge_pass1_mma<<<EB1, 256, EP1_SMEM>>>(x, src, dst, eattr, ew, We1, be1, agg1, E);
    mma_gemm<true><<<gemmGrid, 256>>>(agg1, W11, b11, t1, M, HID, IND);
    mma_gemm<true><<<gemmGrid, 256>>>(t1,   W12, b12, h1, M, HID, HID);

    // ---- layer 2 ----
    cudaMemcpyAsync(agg2, h1, (size_t)M * HID * sizeof(float),
                    cudaMemcpyDeviceToDevice, 0);
    edge_pass2_mma<<<EB2, 256, EP2_SMEM>>>(h1, src, dst, eattr, ew, We2, be2, agg2, E);
    mma_gemm<true><<<gemmGrid, 256>>>(agg2, W21, b21, t1, M, HID, HID);
    mma_gemm<true><<<gemmGrid, 256>>>(t1,   W22, b22, h2, M, HID, HID);

    // ---- output head ----
    mma_gemm<false><<<gemmGrid, 256>>>(h2, Wo, bo, out, M, NTYPES, HID);
}

// round 14
// speedup vs baseline: 2.3468x; 1.1170x over previous
#include <cuda_runtime.h>
#include <cuda_bf16.h>
#include <cstdint>

// Problem constants
#define NNODES 50000
#define IND    64
#define HID    128
#define EDIM   16
#define NTYPES 100

// Scratch (device globals; no runtime allocation allowed)
__device__ float g_agg1[NNODES * IND];    // layer1 accumulator (init = x)
__device__ float g_t1  [NNODES * HID];    // MLP intermediate
__device__ float g_h1  [NNODES * HID];    // after MLP1
__device__ float g_agg2[NNODES * HID];    // layer2 accumulator (init = h1)
__device__ float g_h2  [NNODES * HID];    // after MLP2

// ---------------------------------------------------------------------------
__device__ __forceinline__ void red_add_v4(float* addr, float x, float y, float z, float w) {
    asm volatile("red.global.add.v4.f32 [%0], {%1, %2, %3, %4};"
                 :: "l"(addr), "f"(x), "f"(y), "f"(z), "f"(w) : "memory");
}

__device__ __forceinline__ unsigned f2tf32(float f) {
    unsigned u;
    asm("cvt.rna.tf32.f32 %0, %1;" : "=r"(u) : "f"(f));
    return u;
}

__device__ __forceinline__ void mma_tf32(float* c, const unsigned* a, const unsigned* b) {
    asm volatile(
        "mma.sync.aligned.m16n8k8.row.col.f32.tf32.tf32.f32 "
        "{%0,%1,%2,%3}, {%4,%5,%6,%7}, {%8,%9}, {%0,%1,%2,%3};"
        : "+f"(c[0]), "+f"(c[1]), "+f"(c[2]), "+f"(c[3])
        : "r"(a[0]), "r"(a[1]), "r"(a[2]), "r"(a[3]),
          "r"(b[0]), "r"(b[1]));
}

// ===========================================================================
// Edge pass 2 (feat dim 128), MMA-fused, 64-edge tiles, 128 threads,
// 4 blocks/SM. Phase C uses index preload + 8-deep gather batching.
//   sA 64x17 u32 | sW 128x17 u32 | sE 64x132 f32  = 46848 B
// ===========================================================================
#define PA  17
#define PE2 132
#define EP2_SMEM ((64*PA + 128*PA) * 4 + 64*PE2*4)

__global__ void __launch_bounds__(128, 4)
edge_pass2_mma(const float* __restrict__ h,
               const int* __restrict__ src,
               const int* __restrict__ dst,
               const float* __restrict__ eattr,
               const float* __restrict__ ew,
               const float* __restrict__ We,   // [128,16]
               const float* __restrict__ be,   // [128]
               float* __restrict__ agg,
               int E) {
    extern __shared__ float smem[];
    unsigned* sA = (unsigned*)smem;            // [64][PA]
    unsigned* sW = sA + 64 * PA;               // [128][PA]
    float*    sE = (float*)(sW + 128 * PA);    // [64][PE2]

    const int tid  = threadIdx.x;
    const int lane = tid & 31;
    const int wid  = tid >> 5;     // 0..3
    const int wm   = wid >> 1;     // 0..1 : 32-edge group
    const int wn   = wid & 1;      // 0..1 : 64-feat group
    const int gid  = lane >> 2;    // 0..7
    const int qid  = lane & 3;     // 0..3

    const int lrow = tid >> 1;         // 0..63
    const int lseg = (tid & 1) * 8;    // 0 / 8

    // stage We2 (tf32) once: one row per thread
    {
        const float* p = &We[tid * 16];
        float4 v0 = *(const float4*)p;
        float4 v1 = *(const float4*)(p + 4);
        float4 v2 = *(const float4*)(p + 8);
        float4 v3 = *(const float4*)(p + 12);
        unsigned* dp = &sW[tid * PA];
        dp[0]=f2tf32(v0.x); dp[1]=f2tf32(v0.y); dp[2]=f2tf32(v0.z); dp[3]=f2tf32(v0.w);
        dp[4]=f2tf32(v1.x); dp[5]=f2tf32(v1.y); dp[6]=f2tf32(v1.z); dp[7]=f2tf32(v1.w);
        dp[8]=f2tf32(v2.x); dp[9]=f2tf32(v2.y); dp[10]=f2tf32(v2.z); dp[11]=f2tf32(v2.w);
        dp[12]=f2tf32(v3.x); dp[13]=f2tf32(v3.y); dp[14]=f2tf32(v3.z); dp[15]=f2tf32(v3.w);
    }
    // hoisted bias fragments
    float bb0[8], bb1[8];
#pragma unroll
    for (int nt = 0; nt < 8; nt++) {
        const int n = wn * 64 + nt * 8 + 2 * qid;
        bb0[nt] = __ldg(&be[n]);
        bb1[nt] = __ldg(&be[n + 1]);
    }
    __syncthreads();

    const int numTiles = (E + 63) >> 6;
    for (int t = blockIdx.x; t < numTiles; t += gridDim.x) {
        const int base = t << 6;

        // ---- phase A: stage EA tile (64 x 16 tf32) ----
        {
            const int ge = base + lrow;
            float4 v0 = make_float4(0.f,0.f,0.f,0.f), v1 = v0;
            if (ge < E) {
                const float wt = ew[ge];
                const float* p = &eattr[(long long)ge * 16 + lseg];
                v0 = *(const float4*)p;
                v1 = *(const float4*)(p + 4);
                v0.x*=wt; v0.y*=wt; v0.z*=wt; v0.w*=wt;
                v1.x*=wt; v1.y*=wt; v1.z*=wt; v1.w*=wt;
            }
            unsigned* dp = &sA[lrow * PA + lseg];
            dp[0]=f2tf32(v0.x); dp[1]=f2tf32(v0.y); dp[2]=f2tf32(v0.z); dp[3]=f2tf32(v0.w);
            dp[4]=f2tf32(v1.x); dp[5]=f2tf32(v1.y); dp[6]=f2tf32(v1.z); dp[7]=f2tf32(v1.w);
        }
        __syncthreads();

        // ---- phase B: emb = EA @ We^T + be ----
        float acc[2][8][4];
#pragma unroll
        for (int nt = 0; nt < 8; nt++)
#pragma unroll
            for (int mt = 0; mt < 2; mt++) {
                acc[mt][nt][0] = bb0[nt]; acc[mt][nt][1] = bb1[nt];
                acc[mt][nt][2] = bb0[nt]; acc[mt][nt][3] = bb1[nt];
            }
#pragma unroll
        for (int kk = 0; kk < 16; kk += 8) {
            unsigned af[2][4];
#pragma unroll
            for (int mt = 0; mt < 2; mt++) {
                const int r = wm * 32 + mt * 16 + gid;
                af[mt][0] = sA[(r    ) * PA + kk + qid    ];
                af[mt][1] = sA[(r + 8) * PA + kk + qid    ];
                af[mt][2] = sA[(r    ) * PA + kk + qid + 4];
                af[mt][3] = sA[(r + 8) * PA + kk + qid + 4];
            }
            unsigned bf[8][2];
#pragma unroll
            for (int nt = 0; nt < 8; nt++) {
                const int c = wn * 64 + nt * 8 + gid;
                bf[nt][0] = sW[c * PA + kk + qid    ];
                bf[nt][1] = sW[c * PA + kk + qid + 4];
            }
#pragma unroll
            for (int mt = 0; mt < 2; mt++)
#pragma unroll
                for (int nt = 0; nt < 8; nt++)
                    mma_tf32(acc[mt][nt], af[mt], bf[nt]);
        }
        // fragments -> sE
#pragma unroll
        for (int mt = 0; mt < 2; mt++) {
            const int r0 = wm * 32 + mt * 16 + gid;
#pragma unroll
            for (int nt = 0; nt < 8; nt++) {
                const int n = wn * 64 + nt * 8 + 2 * qid;
                *(float2*)&sE[r0 * PE2 + n]       = make_float2(acc[mt][nt][0], acc[mt][nt][1]);
                *(float2*)&sE[(r0 + 8) * PE2 + n] = make_float2(acc[mt][nt][2], acc[mt][nt][3]);
            }
        }
        __syncthreads();

        // ---- phase C: batched gather + relu + scatter (warp per edge) ----
        // preload this warp's 16 src (lanes 0-15) and 16 dst (lanes 16-31)
        int idx;
        {
            const int l = lane & 15;
            const int ge = base + wid * 16 + l;
            const int* arr = (lane < 16) ? src : dst;
            idx = (ge < E) ? arr[ge] : 0;
        }
        const int f = 4 * lane;
#pragma unroll
        for (int c = 0; c < 2; c++) {
            float4 g[8];
            int dl[8];
#pragma unroll
            for (int j = 0; j < 8; j++) {
                const int s = __shfl_sync(0xffffffffu, idx, c * 8 + j);
                dl[j]       = __shfl_sync(0xffffffffu, idx, 16 + c * 8 + j);
                g[j] = *(const float4*)&h[(long long)s * HID + f];
            }
#pragma unroll
            for (int j = 0; j < 8; j++) {
                const int el = wid * 16 + c * 8 + j;
                if (base + el < E) {
                    const float4 em = *(const float4*)&sE[el * PE2 + f];
                    red_add_v4(&agg[(long long)dl[j] * HID + f],
                               fmaxf(em.x + g[j].x, 0.f), fmaxf(em.y + g[j].y, 0.f),
                               fmaxf(em.z + g[j].z, 0.f), fmaxf(em.w + g[j].w, 0.f));
                }
            }
        }
        __syncthreads();
    }
}

// ===========================================================================
// Edge pass 1 (feat dim 64), MMA-fused, 64-edge tiles, 128 threads.
//   sA 64x17 u32 | sW 64x17 u32 | sE 64x68 f32  = 26112 B
// ===========================================================================
#define PE1 68
#define EP1_SMEM ((64*PA + 64*PA) * 4 + 64*PE1*4)

__global__ void __launch_bounds__(128, 4)
edge_pass1_mma(const float* __restrict__ x,
               const int* __restrict__ src,
               const int* __restrict__ dst,
               const float* __restrict__ eattr,
               const float* __restrict__ ew,
               const float* __restrict__ We,   // [64,16]
               const float* __restrict__ be,   // [64]
               float* __restrict__ agg,
               int E) {
    extern __shared__ float smem[];
    unsigned* sA = (unsigned*)smem;            // [64][PA]
    unsigned* sW = sA + 64 * PA;               // [64][PA]
    float*    sE = (float*)(sW + 64 * PA);     // [64][PE1]

    const int tid  = threadIdx.x;
    const int lane = tid & 31;
    const int wid  = tid >> 5;     // 0..3 : 16-edge group
    const int gid  = lane >> 2;
    const int qid  = lane & 3;

    const int lrow = tid >> 1;
    const int lseg = (tid & 1) * 8;

    // stage We1 (tf32) once (64 rows, one per thread 0..63)
    if (tid < 64) {
        const float* p = &We[tid * 16];
        float4 v0 = *(const float4*)p;
        float4 v1 = *(const float4*)(p + 4);
        float4 v2 = *(const float4*)(p + 8);
        float4 v3 = *(const float4*)(p + 12);
        unsigned* dp = &sW[tid * PA];
        dp[0]=f2tf32(v0.x); dp[1]=f2tf32(v0.y); dp[2]=f2tf32(v0.z); dp[3]=f2tf32(v0.w);
        dp[4]=f2tf32(v1.x); dp[5]=f2tf32(v1.y); dp[6]=f2tf32(v1.z); dp[7]=f2tf32(v1.w);
        dp[8]=f2tf32(v2.x); dp[9]=f2tf32(v2.y); dp[10]=f2tf32(v2.z); dp[11]=f2tf32(v2.w);
        dp[12]=f2tf32(v3.x); dp[13]=f2tf32(v3.y); dp[14]=f2tf32(v3.z); dp[15]=f2tf32(v3.w);
    }
    float bb0[8], bb1[8];
#pragma unroll
    for (int nt = 0; nt < 8; nt++) {
        const int n = nt * 8 + 2 * qid;
        bb0[nt] = __ldg(&be[n]);
        bb1[nt] = __ldg(&be[n + 1]);
    }
    __syncthreads();

    const int numTiles = (E + 63) >> 6;
    for (int t = blockIdx.x; t < numTiles; t += gridDim.x) {
        const int base = t << 6;

        // ---- stage EA tile ----
        {
            const int ge = base + lrow;
            float4 v0 = make_float4(0.f,0.f,0.f,0.f), v1 = v0;
            if (ge < E) {
                const float wt = ew[ge];
                const float* p = &eattr[(long long)ge * 16 + lseg];
                v0 = *(const float4*)p;
                v1 = *(const float4*)(p + 4);
                v0.x*=wt; v0.y*=wt; v0.z*=wt; v0.w*=wt;
                v1.x*=wt; v1.y*=wt; v1.z*=wt; v1.w*=wt;
            }
            unsigned* dp = &sA[lrow * PA + lseg];
            dp[0]=f2tf32(v0.x); dp[1]=f2tf32(v0.y); dp[2]=f2tf32(v0.z); dp[3]=f2tf32(v0.w);
            dp[4]=f2tf32(v1.x); dp[5]=f2tf32(v1.y); dp[6]=f2tf32(v1.z); dp[7]=f2tf32(v1.w);
        }
        __syncthreads();

        // ---- MMA: 16 edges (this warp) x 64 feats ----
        float acc[8][4];
#pragma unroll
        for (int nt = 0; nt < 8; nt++) {
            acc[nt][0] = bb0[nt]; acc[nt][1] = bb1[nt];
            acc[nt][2] = bb0[nt]; acc[nt][3] = bb1[nt];
        }
#pragma unroll
        for (int kk = 0; kk < 16; kk += 8) {
            unsigned af[4];
            const int r = wid * 16 + gid;
            af[0] = sA[(r    ) * PA + kk + qid    ];
            af[1] = sA[(r + 8) * PA + kk + qid    ];
            af[2] = sA[(r    ) * PA + kk + qid + 4];
            af[3] = sA[(r + 8) * PA + kk + qid + 4];
            unsigned bf[8][2];
#pragma unroll
            for (int nt = 0; nt < 8; nt++) {
                const int c = nt * 8 + gid;
                bf[nt][0] = sW[c * PA + kk + qid    ];
                bf[nt][1] = sW[c * PA + kk + qid + 4];
            }
#pragma unroll
            for (int nt = 0; nt < 8; nt++)
                mma_tf32(acc[nt], af, bf[nt]);
        }
        {
            const int r0 = wid * 16 + gid;
#pragma unroll
            for (int nt = 0; nt < 8; nt++) {
                const int n = nt * 8 + 2 * qid;
                *(float2*)&sE[r0 * PE1 + n]       = make_float2(acc[nt][0], acc[nt][1]);
                *(float2*)&sE[(r0 + 8) * PE1 + n] = make_float2(acc[nt][2], acc[nt][3]);
            }
        }
        __syncthreads();

        // ---- batched gather + relu + scatter: half-warp per edge ----
        int idx;
        {
            const int l = lane & 15;
            const int ge = base + wid * 16 + l;
            const int* arr = (lane < 16) ? src : dst;
            idx = (ge < E) ? arr[ge] : 0;
        }
        const int half = lane >> 4;          // 0/1
        const int f = (lane & 15) * 4;       // 0..60
#pragma unroll
        for (int c = 0; c < 2; c++) {
            float4 g[4];
            int dl[4];
#pragma unroll
            for (int j = 0; j < 4; j++) {
                const int eo = c * 8 + 2 * j + half;          // 0..15
                const int s = __shfl_sync(0xffffffffu, idx, eo);
                dl[j]       = __shfl_sync(0xffffffffu, idx, 16 + eo);
                g[j] = *(const float4*)&x[(long long)s * IND + f];
            }
#pragma unroll
            for (int j = 0; j < 4; j++) {
                const int el = wid * 16 + c * 8 + 2 * j + half;
                if (base + el < E) {
                    const float4 em = *(const float4*)&sE[el * PE1 + f];
                    red_add_v4(&agg[(long long)dl[j] * IND + f],
                               fmaxf(em.x + g[j].x, 0.f), fmaxf(em.y + g[j].y, 0.f),
                               fmaxf(em.z + g[j].z, 0.f), fmaxf(em.w + g[j].w, 0.f));
                }
            }
        }
        __syncthreads();
    }
}

// ---------------------------------------------------------------------------
// TF32 tensor-core GEMM: C[m,n] = act( sum_k A[m,k]*W[n,k] + bias[n] )
// (unchanged)
// ---------------------------------------------------------------------------
#define SPITCH 20

template <bool RELU>
__global__ void __launch_bounds__(256, 2)
mma_gemm(const float* __restrict__ A,
         const float* __restrict__ W,
         const float* __restrict__ bias,
         float* __restrict__ C,
         int M, int N, int K) {
    __shared__ unsigned As[128 * SPITCH];
    __shared__ unsigned Ws[128 * SPITCH];

    const int tid  = threadIdx.x;
    const int lane = tid & 31;
    const int wid  = tid >> 5;
    const int wm   = wid >> 1;
    const int wn   = wid & 1;
    const int m0   = blockIdx.y * 128;

    const int lrow = tid >> 1;
    const int lseg = (tid & 1) * 8;

    const int gid  = lane >> 2;
    const int qid  = lane & 3;

    float acc[2][8][4];
#pragma unroll
    for (int i = 0; i < 2; i++)
#pragma unroll
        for (int j = 0; j < 8; j++)
#pragma unroll
            for (int v = 0; v < 4; v++) acc[i][j][v] = 0.f;

    for (int k0 = 0; k0 < K; k0 += 16) {
        {
            const int r = m0 + lrow;
            float4 v0 = make_float4(0.f,0.f,0.f,0.f), v1 = v0;
            if (r < M) {
                const float* p = &A[(long long)r * K + k0 + lseg];
                v0 = *(const float4*)p;
                v1 = *(const float4*)(p + 4);
            }
            unsigned* dstp = &As[lrow * SPITCH + lseg];
            dstp[0]=f2tf32(v0.x); dstp[1]=f2tf32(v0.y); dstp[2]=f2tf32(v0.z); dstp[3]=f2tf32(v0.w);
            dstp[4]=f2tf32(v1.x); dstp[5]=f2tf32(v1.y); dstp[6]=f2tf32(v1.z); dstp[7]=f2tf32(v1.w);
        }
        {
            const int r = lrow;
            float4 v0 = make_float4(0.f,0.f,0.f,0.f), v1 = v0;
            if (r < N) {
                const float* p = &W[(long long)r * K + k0 + lseg];
                v0 = *(const float4*)p;
                v1 = *(const float4*)(p + 4);
            }
            unsigned* dstp = &Ws[lrow * SPITCH + lseg];
            dstp[0]=f2tf32(v0.x); dstp[1]=f2tf32(v0.y); dstp[2]=f2tf32(v0.z); dstp[3]=f2tf32(v0.w);
            dstp[4]=f2tf32(v1.x); dstp[5]=f2tf32(v1.y); dstp[6]=f2tf32(v1.z); dstp[7]=f2tf32(v1.w);
        }
        __syncthreads();

#pragma unroll
        for (int kk = 0; kk < 16; kk += 8) {
            unsigned af[2][4];
#pragma unroll
            for (int mt = 0; mt < 2; mt++) {
                const int r = wm * 32 + mt * 16 + gid;
                af[mt][0] = As[(r    ) * SPITCH + kk + qid    ];
                af[mt][1] = As[(r + 8) * SPITCH + kk + qid    ];
                af[mt][2] = As[(r    ) * SPITCH + kk + qid + 4];
                af[mt][3] = As[(r + 8) * SPITCH + kk + qid + 4];
            }
            unsigned bf[8][2];
#pragma unroll
            for (int nt = 0; nt < 8; nt++) {
                const int c = wn * 64 + nt * 8 + gid;
                bf[nt][0] = Ws[c * SPITCH + kk + qid    ];
                bf[nt][1] = Ws[c * SPITCH + kk + qid + 4];
            }
#pragma unroll
            for (int mt = 0; mt < 2; mt++)
#pragma unroll
                for (int nt = 0; nt < 8; nt++)
                    mma_tf32(acc[mt][nt], af[mt], bf[nt]);
        }
        __syncthreads();
    }

#pragma unroll
    for (int mt = 0; mt < 2; mt++) {
        const int rbase = m0 + wm * 32 + mt * 16 + gid;
#pragma unroll
        for (int nt = 0; nt < 8; nt++) {
            const int n = wn * 64 + nt * 8 + 2 * qid;
#pragma unroll
            for (int half = 0; half < 2; half++) {
                const int m = rbase + half * 8;
                if (m >= M) continue;
                float v0 = acc[mt][nt][2 * half + 0];
                float v1 = acc[mt][nt][2 * half + 1];
                if (n < N) {
                    float o = v0 + bias[n];
                    if (RELU) o = fmaxf(o, 0.f);
                    C[(long long)m * N + n] = o;
                }
                if (n + 1 < N) {
                    float o = v1 + bias[n + 1];
                    if (RELU) o = fmaxf(o, 0.f);
                    C[(long long)m * N + n + 1] = o;
                }
            }
        }
    }
}

// ---------------------------------------------------------------------------
extern "C" void kernel_launch(void* const* d_in, const int* in_sizes, int n_in,
                              void* d_out, int out_size) {
    const float*      x     = (const float*)d_in[0];
    const int*        ei    = (const int*)d_in[1];        // int32 (JAX x64 disabled)
    const float*      eattr = (const float*)d_in[2];
    const float*      ew    = (const float*)d_in[3];
    const float*      We1   = (const float*)d_in[4];
    const float*      be1   = (const float*)d_in[5];
    const float*      W11   = (const float*)d_in[6];
    const float*      b11   = (const float*)d_in[7];
    const float*      W12   = (const float*)d_in[8];
    const float*      b12   = (const float*)d_in[9];
    const float*      We2   = (const float*)d_in[10];
    const float*      be2   = (const float*)d_in[11];
    const float*      W21   = (const float*)d_in[12];
    const float*      b21   = (const float*)d_in[13];
    const float*      W22   = (const float*)d_in[14];
    const float*      b22   = (const float*)d_in[15];
    const float*      Wo    = (const float*)d_in[16];
    const float*      bo    = (const float*)d_in[17];
    float*            out   = (float*)d_out;

    const int E = in_sizes[1] / 2;
    const int* src = ei;
    const int* dst = ei + E;

    float *agg1, *t1, *h1, *agg2, *h2;
    cudaGetSymbolAddress((void**)&agg1, g_agg1);
    cudaGetSymbolAddress((void**)&t1,   g_t1);
    cudaGetSymbolAddress((void**)&h1,   g_h1);
    cudaGetSymbolAddress((void**)&agg2, g_agg2);
    cudaGetSymbolAddress((void**)&h2,   g_h2);

    // host-side attribute sets (capture-safe, stateless)
    cudaFuncSetAttribute(edge_pass1_mma,
                         cudaFuncAttributeMaxDynamicSharedMemorySize, EP1_SMEM);
    cudaFuncSetAttribute(edge_pass2_mma,
                         cudaFuncAttributeMaxDynamicSharedMemorySize, EP2_SMEM);

    const int M = NNODES;
    const dim3 gemmGrid(1, (M + 127) / 128);
    const int EB = 148 * 4;    // matches __launch_bounds__(128,4)

    // ---- layer 1 ----
    cudaMemcpyAsync(agg1, x, (size_t)M * IND * sizeof(float),
                    cudaMemcpyDeviceToDevice, 0);
    edge_pass1_mma<<<EB, 128, EP1_SMEM>>>(x, src, dst, eattr, ew, We1, be1, agg1, E);
    mma_gemm<true><<<gemmGrid, 256>>>(agg1, W11, b11, t1, M, HID, IND);
    mma_gemm<true><<<gemmGrid, 256>>>(t1,   W12, b12, h1, M, HID, HID);

    // ---- layer 2 ----
    cudaMemcpyAsync(agg2, h1, (size_t)M * HID * sizeof(float),
                    cudaMemcpyDeviceToDevice, 0);
    edge_pass2_mma<<<EB, 128, EP2_SMEM>>>(h1, src, dst, eattr, ew, We2, be2, agg2, E);
    mma_gemm<true><<<gemmGrid, 256>>>(agg2, W21, b21, t1, M, HID, HID);
    mma_gemm<true><<<gemmGrid, 256>>>(t1,   W22, b22, h2, M, HID, HID);

    // ---- output head ----
    mma_gemm<false><<<gemmGrid, 256>>>(h2, Wo, bo, out, M, NTYPES, HID);
}